// round 13
// baseline (speedup 1.0000x reference)
#include <cuda_runtime.h>
#include <cuda_bf16.h>
#include <cstdint>

#define BB 64
#define NP 1024
#define LL 64
#define HH 128
#define W1K 67
#define TN 128
#define NT (BB * 8)       // 512 tiles of 128 points
#define MLP_GRID 148
#define KS 136            // bf16 elements per row (272B, 16B-aligned stride)
#define H2ROW 132         // fp32 row stride for h2

__device__ float g_acc[3];
__device__ float g_w1l[BB * HH];

// W1L precompute + zero accumulators (block 0)
__global__ void __launch_bounds__(128) w1l_kernel(
    const float* __restrict__ latent, const float* __restrict__ W1,
    const float* __restrict__ b1)
{
    __shared__ float slat[LL];
    if (blockIdx.x == 0 && threadIdx.x < 3) g_acc[threadIdx.x] = 0.0f;
    const int b = blockIdx.x, o = threadIdx.x;
    if (o < LL) slat[o] = latent[b * LL + o];
    __syncthreads();
    float acc = b1[o];
    const float* wrow = W1 + o * W1K + 3;
    #pragma unroll 8
    for (int l = 0; l < LL; l++) acc = fmaf(wrow[l], slat[l], acc);
    g_w1l[b * HH + o] = acc;
}

__device__ __forceinline__ float block_sum(float v, float* scratch) {
    #pragma unroll
    for (int off = 16; off; off >>= 1) v += __shfl_down_sync(0xffffffffu, v, off);
    int lane = threadIdx.x & 31, w = threadIdx.x >> 5;
    if (lane == 0) scratch[w] = v;
    __syncthreads();
    int nw = blockDim.x >> 5;
    v = (threadIdx.x < nw) ? scratch[threadIdx.x] : 0.0f;
    if (w == 0) {
        #pragma unroll
        for (int off = 16; off; off >>= 1) v += __shfl_down_sync(0xffffffffu, v, off);
    }
    return v;
}

__device__ __forceinline__ uint32_t smem_u32(const void* p) {
    uint32_t a;
    asm("{ .reg .u64 t; cvta.to.shared.u64 t, %1; cvt.u32.u64 %0, t; }"
        : "=r"(a) : "l"(p));
    return a;
}
__device__ __forceinline__ void ldmx4(uint32_t* r, uint32_t addr) {
    asm volatile("ldmatrix.sync.aligned.m8n8.x4.shared.b16 {%0,%1,%2,%3}, [%4];"
                 : "=r"(r[0]), "=r"(r[1]), "=r"(r[2]), "=r"(r[3]) : "r"(addr));
}
__device__ __forceinline__ void ldmx2(uint32_t* r, uint32_t addr) {
    asm volatile("ldmatrix.sync.aligned.m8n8.x2.shared.b16 {%0,%1}, [%2];"
                 : "=r"(r[0]), "=r"(r[1]) : "r"(addr));
}
__device__ __forceinline__ void mma_bf16(float* c, const uint32_t* a,
                                         const uint32_t* b) {
    asm volatile(
        "mma.sync.aligned.m16n8k16.row.col.f32.bf16.bf16.f32 "
        "{%0,%1,%2,%3}, {%4,%5,%6,%7}, {%8,%9}, {%0,%1,%2,%3};"
        : "+f"(c[0]), "+f"(c[1]), "+f"(c[2]), "+f"(c[3])
        : "r"(a[0]), "r"(a[1]), "r"(a[2]), "r"(a[3]), "r"(b[0]), "r"(b[1]));
}
__device__ __forceinline__ void mma_k8(float* c, const uint32_t* a, uint32_t b) {
    asm volatile(
        "mma.sync.aligned.m16n8k8.row.col.f32.bf16.bf16.f32 "
        "{%0,%1,%2,%3}, {%4,%5}, {%6}, {%0,%1,%2,%3};"
        : "+f"(c[0]), "+f"(c[1]), "+f"(c[2]), "+f"(c[3])
        : "r"(a[0]), "r"(a[1]), "r"(b));
}
__device__ __forceinline__ void mma_k8_z(float* c, const uint32_t* a, uint32_t b) {
    asm volatile(
        "mma.sync.aligned.m16n8k8.row.col.f32.bf16.bf16.f32 "
        "{%0,%1,%2,%3}, {%4,%5}, {%6}, {%7,%8,%9,%10};"
        : "=f"(c[0]), "=f"(c[1]), "=f"(c[2]), "=f"(c[3])
        : "r"(a[0]), "r"(a[1]), "r"(b),
          "f"(0.0f), "f"(0.0f), "f"(0.0f), "f"(0.0f));
}
__device__ __forceinline__ unsigned pack_bf2(__nv_bfloat16 a, __nv_bfloat16 b) {
    return (unsigned)__bfloat16_as_ushort(a) |
           ((unsigned)__bfloat16_as_ushort(b) << 16);
}

// SMEM byte offsets (mlp)
#define OFF_W2HI 0
#define OFF_W2LO 34816
#define OFF_HHI  69632
#define OFF_HLO  104448
#define OFF_H2   69632
#define OFF_MISC 139264

// ---------------------------------------------------------------------------
// Persistent MLP (R11 body, best known): split-bf16 mma.sync GEMM2.
// ---------------------------------------------------------------------------
__global__ void __launch_bounds__(256) mlp_kernel(
    const float* __restrict__ pc, const float* __restrict__ pc_gt,
    const float* __restrict__ W2, const float* __restrict__ b2,
    const float* __restrict__ W1,
    const float* __restrict__ W3, const float* __restrict__ b3,
    float* __restrict__ out_est)
{
    extern __shared__ float smf[];
    char* sb = (char*)smf;
    __nv_bfloat16* w2hi = (__nv_bfloat16*)(sb + OFF_W2HI);
    __nv_bfloat16* w2lo = (__nv_bfloat16*)(sb + OFF_W2LO);
    __nv_bfloat16* hhi  = (__nv_bfloat16*)(sb + OFF_HHI);
    __nv_bfloat16* hlo  = (__nv_bfloat16*)(sb + OFF_HLO);
    float* s_h2 = (float*)(sb + OFF_H2);
    float* misc = (float*)(sb + OFF_MISC);
    float* swx  = misc;
    float* swl  = swx + 384;
    float* sb2  = swl + 128;
    float* sw3  = sb2 + 128;
    float* sb3  = sw3 + 384;
    float* s_x  = sb3 + 4;
    float* sred = s_x + 384;

    const int tid = threadIdx.x;
    const int lane = tid & 31;
    const int wid = tid >> 5;

    {
        const int o = tid & 127, kh = tid >> 7;
        const float* w2r = W2 + o * HH;
        for (int k = kh * 64; k < kh * 64 + 64; k += 2) {
            float w0 = w2r[k], w1 = w2r[k + 1];
            __nv_bfloat16 h0 = __float2bfloat16(w0);
            __nv_bfloat16 h1 = __float2bfloat16(w1);
            *(unsigned*)&w2hi[o * KS + k] = pack_bf2(h0, h1);
            *(unsigned*)&w2lo[o * KS + k] =
                pack_bf2(__float2bfloat16(w0 - __bfloat162float(h0)),
                         __float2bfloat16(w1 - __bfloat162float(h1)));
        }
    }
    for (int i = tid; i < 384; i += 256) {
        int k = i >> 7, o = i & 127;
        swx[k * 128 + o] = W1[o * W1K + k];
        sw3[i] = W3[i];
    }
    if (tid < 128) sb2[tid] = b2[tid];
    if (tid < 3) sb3[tid] = b3[tid];
    __syncthreads();

    const uint32_t u_w2hi = smem_u32(w2hi);
    const uint32_t u_w2lo = smem_u32(w2lo);
    const uint32_t u_hhi  = smem_u32(hhi);
    const uint32_t u_hlo  = smem_u32(hlo);

    const int lr = lane & 7;
    const int aq = lane >> 3;
    const int arow_off = ((aq & 1) << 3) + lr;
    const int acol_off = (aq >> 1) << 3;
    const int bl15 = lane & 15;
    const int brow_off = bl15 & 7;
    const int bcol_off = (bl15 >> 3) << 3;

    const int o0 = wid * 16;
    float l2acc = 0.0f;

    for (int t = blockIdx.x; t < NT; t += MLP_GRID) {
        const int b  = t >> 3;
        const int n0 = (t & 7) * TN;

        __syncthreads();
        for (int i = tid; i < 384; i += 256) {
            int k = i >> 7, n = i & 127;
            s_x[k * 128 + n] = pc[(b * 3 + k) * NP + n0 + n];
        }
        if (tid < 128) swl[tid] = g_w1l[b * HH + tid];
        __syncthreads();

        {
            const int n = tid & 127, kh = tid >> 7;
            const float x0 = s_x[n], x1 = s_x[128 + n], x2 = s_x[256 + n];
            #pragma unroll
            for (int k = kh * 64; k < kh * 64 + 64; k += 2) {
                float h0 = fmaxf(fmaf(swx[k], x0, fmaf(swx[128 + k], x1,
                             fmaf(swx[256 + k], x2, swl[k]))), 0.0f);
                float h1v = fmaxf(fmaf(swx[k + 1], x0, fmaf(swx[129 + k], x1,
                              fmaf(swx[257 + k], x2, swl[k + 1]))), 0.0f);
                __nv_bfloat16 bh0 = __float2bfloat16(h0);
                __nv_bfloat16 bh1 = __float2bfloat16(h1v);
                *(unsigned*)&hhi[n * KS + k] = pack_bf2(bh0, bh1);
                *(unsigned*)&hlo[n * KS + k] =
                    pack_bf2(__float2bfloat16(h0 - __bfloat162float(bh0)),
                             __float2bfloat16(h1v - __bfloat162float(bh1)));
            }
        }
        __syncthreads();

        float C[16][4];
        #pragma unroll
        for (int nt = 0; nt < 16; nt++)
            #pragma unroll
            for (int j = 0; j < 4; j++) C[nt][j] = 0.0f;

        #pragma unroll
        for (int k8 = 0; k8 < 8; k8++) {
            const int k0 = k8 * 16;
            const uint32_t aoff = (uint32_t)(o0 + arow_off) * 272u +
                                  (uint32_t)(k0 + acol_off) * 2u;
            uint32_t ah[4], al[4];
            ldmx4(ah, u_w2hi + aoff);
            ldmx4(al, u_w2lo + aoff);
            #pragma unroll
            for (int nt = 0; nt < 16; nt++) {
                const uint32_t boff = (uint32_t)(nt * 8 + brow_off) * 272u +
                                      (uint32_t)(k0 + bcol_off) * 2u;
                uint32_t bh[2], bl[2];
                ldmx2(bh, u_hhi + boff);
                ldmx2(bl, u_hlo + boff);
                mma_bf16(C[nt], ah, bh);
                mma_bf16(C[nt], ah, bl);
                mma_bf16(C[nt], al, bh);
            }
        }
        __syncthreads();

        {
            const int r = lane >> 2;
            const int cp = (lane & 3) * 2;
            const float bo  = sb2[o0 + r];
            const float bo8 = sb2[o0 + r + 8];
            #pragma unroll
            for (int nt = 0; nt < 16; nt++) {
                int n = nt * 8 + cp;
                s_h2[(o0 + r) * H2ROW + n]     = fmaxf(C[nt][0] + bo, 0.0f);
                s_h2[(o0 + r) * H2ROW + n + 1] = fmaxf(C[nt][1] + bo, 0.0f);
                s_h2[(o0 + r + 8) * H2ROW + n]     = fmaxf(C[nt][2] + bo8, 0.0f);
                s_h2[(o0 + r + 8) * H2ROW + n + 1] = fmaxf(C[nt][3] + bo8, 0.0f);
            }
        }
        __syncthreads();

        if (tid < TN) {
            int n = tid, g = n0 + n;
            float o0v = sb3[0], o1v = sb3[1], o2v = sb3[2];
            #pragma unroll 4
            for (int k = 0; k < HH; k++) {
                float hv = s_h2[k * H2ROW + n];
                o0v = fmaf(sw3[k], hv, o0v);
                o1v = fmaf(sw3[128 + k], hv, o1v);
                o2v = fmaf(sw3[256 + k], hv, o2v);
            }
            int base = (b * 3) * NP + g;
            float e0 = pc[base] - o0v;
            float e1 = pc[base + NP] - o1v;
            float e2 = pc[base + 2 * NP] - o2v;
            out_est[base] = e0;
            out_est[base + NP] = e1;
            out_est[base + 2 * NP] = e2;
            float d0 = pc_gt[base] - e0;
            float d1 = pc_gt[base + NP] - e1;
            float d2 = pc_gt[base + 2 * NP] - e2;
            l2acc += fmaf(d0, d0, fmaf(d1, d1, d2 * d2));
        }
    }

    __syncthreads();
    float s = block_sum(l2acc, sred);
    if (tid == 0) atomicAdd(&g_acc[2], s);
}

// SMEM byte offsets (chamfer)
#define CH_BH 0
#define CH_BL 16384
#define CH_AH 32768
#define CH_AL 49152
#define CH_Q2 65536
#define CH_RED 69632
#define CH_SMEM 69696

// ---------------------------------------------------------------------------
// Chamfer via tensor cores: C[q][m] = |p|^2 - 2*dot(q,p) as one split-bf16
// GEMM (A[q]={-2q,1,0..}, B[m]={p,|p|^2,0..}, k=8), then d = a^2 + min_m C.
// grid (64, 2), 256 threads.
// ---------------------------------------------------------------------------
__global__ void __launch_bounds__(256) chamfer_kernel(
    const float* __restrict__ pc_gt, const float* __restrict__ est)
{
    extern __shared__ float smf[];
    char* cs = (char*)smf;
    float* sQ2  = (float*)(cs + CH_Q2);
    float* sred = (float*)(cs + CH_RED);
    const uint32_t u_bh = smem_u32(cs + CH_BH);
    const uint32_t u_bl = smem_u32(cs + CH_BL);
    const uint32_t u_ah = smem_u32(cs + CH_AH);
    const uint32_t u_al = smem_u32(cs + CH_AL);

    const int b = blockIdx.x;
    const int dir = blockIdx.y;
    const float* rows  = dir ? est   : pc_gt;
    const float* other = dir ? pc_gt : est;
    const int base = b * 3 * NP;
    const int tid  = threadIdx.x;
    const int lane = tid & 31;
    const int wid  = tid >> 5;
    const __nv_bfloat16 one_bf = __float2bfloat16(1.0f);
    const __nv_bfloat16 zero_bf = __float2bfloat16(0.0f);

    // ---- prep: split-bf16 operand tiles ----
    for (int i = tid; i < NP; i += 256) {
        float px = other[base + i];
        float py = other[base + NP + i];
        float pz = other[base + 2 * NP + i];
        float p2 = fmaf(px, px, fmaf(py, py, pz * pz));
        __nv_bfloat16 hx = __float2bfloat16(px);
        __nv_bfloat16 hy = __float2bfloat16(py);
        __nv_bfloat16 hz = __float2bfloat16(pz);
        __nv_bfloat16 h2 = __float2bfloat16(p2);
        uint4 vh = make_uint4(pack_bf2(hx, hy), pack_bf2(hz, h2), 0u, 0u);
        *(uint4*)(cs + CH_BH + i * 16) = vh;
        uint4 vl = make_uint4(
            pack_bf2(__float2bfloat16(px - __bfloat162float(hx)),
                     __float2bfloat16(py - __bfloat162float(hy))),
            pack_bf2(__float2bfloat16(pz - __bfloat162float(hz)),
                     __float2bfloat16(p2 - __bfloat162float(h2))), 0u, 0u);
        *(uint4*)(cs + CH_BL + i * 16) = vl;

        float qx = rows[base + i];
        float qy = rows[base + NP + i];
        float qz = rows[base + 2 * NP + i];
        sQ2[i] = fmaf(qx, qx, fmaf(qy, qy, qz * qz));
        float ax = -2.0f * qx, ay = -2.0f * qy, az = -2.0f * qz;
        __nv_bfloat16 gx = __float2bfloat16(ax);
        __nv_bfloat16 gy = __float2bfloat16(ay);
        __nv_bfloat16 gz = __float2bfloat16(az);
        uint4 ah = make_uint4(pack_bf2(gx, gy), pack_bf2(gz, one_bf), 0u, 0u);
        *(uint4*)(cs + CH_AH + i * 16) = ah;
        uint4 al = make_uint4(
            pack_bf2(__float2bfloat16(ax - __bfloat162float(gx)),
                     __float2bfloat16(ay - __bfloat162float(gy))),
            pack_bf2(__float2bfloat16(az - __bfloat162float(gz)), zero_bf),
            0u, 0u);
        *(uint4*)(cs + CH_AL + i * 16) = al;
    }
    __syncthreads();

    // ---- main: per warp, q-strips of 16; scan all 1024 points via mma ----
    float tsum = 0.0f;
    const uint32_t a_lane_off = (uint32_t)(lane & 15) * 16u;
    const uint32_t b_lane_off = (uint32_t)lane * 16u;

    #pragma unroll 1
    for (int pass = 0; pass < 8; pass++) {
        const int q0 = pass * 128 + wid * 16;
        uint32_t Ah[2], Al[2];
        ldmx2(Ah, u_ah + (uint32_t)q0 * 16u + a_lane_off);
        ldmx2(Al, u_al + (uint32_t)q0 * 16u + a_lane_off);

        float m0 = 3.4e38f, m8 = 3.4e38f;
        #pragma unroll 4
        for (int g = 0; g < 32; g++) {
            uint32_t Bh4[4], Bl4[4];
            const uint32_t goff = (uint32_t)g * 512u + b_lane_off;
            ldmx4(Bh4, u_bh + goff);
            ldmx4(Bl4, u_bl + goff);
            #pragma unroll
            for (int j = 0; j < 4; j++) {
                float C[4];
                mma_k8_z(C, Ah, Bh4[j]);
                mma_k8(C, Ah, Bl4[j]);
                mma_k8(C, Al, Bh4[j]);
                m0 = fminf(m0, fminf(C[0], C[1]));
                m8 = fminf(m8, fminf(C[2], C[3]));
            }
        }
        m0 = fminf(m0, __shfl_xor_sync(0xffffffffu, m0, 1));
        m0 = fminf(m0, __shfl_xor_sync(0xffffffffu, m0, 2));
        m8 = fminf(m8, __shfl_xor_sync(0xffffffffu, m8, 1));
        m8 = fminf(m8, __shfl_xor_sync(0xffffffffu, m8, 2));
        if ((lane & 3) == 0) {
            int r = lane >> 2;
            tsum += (sQ2[q0 + r] + m0) + (sQ2[q0 + 8 + r] + m8);
        }
    }

    float s = block_sum(tsum, sred);
    if (tid == 0) atomicAdd(&g_acc[dir], s);
}

__global__ void final_kernel(float* __restrict__ out) {
    float ch = (g_acc[0] + g_acc[1]) * (1.0f / (float)(BB * NP));
    float l2 = g_acc[2] * (1.0f / (float)(BB * 3 * NP));
    out[0] = 0.1f * ch + 0.9f * l2;
    out[1] = ch;
    out[2] = l2;
}

extern "C" void kernel_launch(void* const* d_in, const int* in_sizes, int n_in,
                              void* d_out, int out_size) {
    const float* pc    = (const float*)d_in[0];
    const float* pc_gt = (const float*)d_in[1];
    const float* lat   = (const float*)d_in[2];
    const float* W1    = (const float*)d_in[3];
    const float* b1    = (const float*)d_in[4];
    const float* W2    = (const float*)d_in[5];
    const float* b2    = (const float*)d_in[6];
    const float* W3    = (const float*)d_in[7];
    const float* b3    = (const float*)d_in[8];
    float* out = (float*)d_out;

    size_t smem_mlp = OFF_MISC + (size_t)(384 + 128 + 128 + 384 + 4 + 384 + 16)
                                 * sizeof(float);
    (void)cudaFuncSetAttribute(mlp_kernel,
                               cudaFuncAttributeMaxDynamicSharedMemorySize,
                               (int)smem_mlp);
    (void)cudaFuncSetAttribute(chamfer_kernel,
                               cudaFuncAttributeMaxDynamicSharedMemorySize,
                               CH_SMEM);

    w1l_kernel<<<BB, 128>>>(lat, W1, b1);
    mlp_kernel<<<MLP_GRID, 256, smem_mlp>>>(pc, pc_gt, W2, b2, W1, W3, b3,
                                            out + 3);
    chamfer_kernel<<<dim3(BB, 2), 256, CH_SMEM>>>(pc_gt, out + 3);
    final_kernel<<<1, 1>>>(out);
}

// round 14
// speedup vs baseline: 1.2443x; 1.2443x over previous
#include <cuda_runtime.h>
#include <cuda_fp16.h>
#include <cstdint>

#define BB 64
#define NP 1024
#define LL 64
#define HH 128
#define W1K 67
#define TN 128
#define NT (BB * 8)       // 512 tiles of 128 points
#define MLP_GRID 148
#define KS 136            // fp16 elements per row (272B stride)
#define H2ROW 132         // fp32 row stride for h2

__device__ float g_acc[3];
__device__ unsigned g_done;
__device__ float g_w1l[BB * HH];

// W1L precompute + zero accumulators (block 0)
__global__ void __launch_bounds__(128) w1l_kernel(
    const float* __restrict__ latent, const float* __restrict__ W1,
    const float* __restrict__ b1)
{
    __shared__ float slat[LL];
    if (blockIdx.x == 0 && threadIdx.x < 4) {
        if (threadIdx.x < 3) g_acc[threadIdx.x] = 0.0f;
        else g_done = 0u;
    }
    const int b = blockIdx.x, o = threadIdx.x;
    if (o < LL) slat[o] = latent[b * LL + o];
    __syncthreads();
    float acc = b1[o];
    const float* wrow = W1 + o * W1K + 3;
    #pragma unroll 8
    for (int l = 0; l < LL; l++) acc = fmaf(wrow[l], slat[l], acc);
    g_w1l[b * HH + o] = acc;
}

__device__ __forceinline__ float block_sum(float v, float* scratch) {
    #pragma unroll
    for (int off = 16; off; off >>= 1) v += __shfl_down_sync(0xffffffffu, v, off);
    int lane = threadIdx.x & 31, w = threadIdx.x >> 5;
    if (lane == 0) scratch[w] = v;
    __syncthreads();
    int nw = blockDim.x >> 5;
    v = (threadIdx.x < nw) ? scratch[threadIdx.x] : 0.0f;
    if (w == 0) {
        #pragma unroll
        for (int off = 16; off; off >>= 1) v += __shfl_down_sync(0xffffffffu, v, off);
    }
    return v;
}

__device__ __forceinline__ uint32_t smem_u32(const void* p) {
    uint32_t a;
    asm("{ .reg .u64 t; cvta.to.shared.u64 t, %1; cvt.u32.u64 %0, t; }"
        : "=r"(a) : "l"(p));
    return a;
}
__device__ __forceinline__ void ldmx4(uint32_t* r, uint32_t addr) {
    asm volatile("ldmatrix.sync.aligned.m8n8.x4.shared.b16 {%0,%1,%2,%3}, [%4];"
                 : "=r"(r[0]), "=r"(r[1]), "=r"(r[2]), "=r"(r[3]) : "r"(addr));
}
__device__ __forceinline__ void ldmx2(uint32_t* r, uint32_t addr) {
    asm volatile("ldmatrix.sync.aligned.m8n8.x2.shared.b16 {%0,%1}, [%2];"
                 : "=r"(r[0]), "=r"(r[1]) : "r"(addr));
}
__device__ __forceinline__ void mma_f16(float* c, const uint32_t* a,
                                        const uint32_t* b) {
    asm volatile(
        "mma.sync.aligned.m16n8k16.row.col.f32.f16.f16.f32 "
        "{%0,%1,%2,%3}, {%4,%5,%6,%7}, {%8,%9}, {%0,%1,%2,%3};"
        : "+f"(c[0]), "+f"(c[1]), "+f"(c[2]), "+f"(c[3])
        : "r"(a[0]), "r"(a[1]), "r"(a[2]), "r"(a[3]), "r"(b[0]), "r"(b[1]));
}
__device__ __forceinline__ unsigned pack_hf2(__half a, __half b) {
    return (unsigned)__half_as_ushort(a) |
           ((unsigned)__half_as_ushort(b) << 16);
}

// SMEM byte offsets (mlp): no overlays, plenty of room (178 KB < 227 KB)
#define OFF_W2HI 0
#define OFF_W2LO 34816
#define OFF_HHI  69632
#define OFF_H2   104448
#define OFF_MISC 172032

// ---------------------------------------------------------------------------
// Persistent MLP: fp16 2-product split GEMM2 (W2=Ah+Al fp16, h=fp16).
// 148 CTAs x 256 thr over 512 tiles of 128 points.
// ---------------------------------------------------------------------------
__global__ void __launch_bounds__(256) mlp_kernel(
    const float* __restrict__ pc, const float* __restrict__ pc_gt,
    const float* __restrict__ W2, const float* __restrict__ b2,
    const float* __restrict__ W1,
    const float* __restrict__ W3, const float* __restrict__ b3,
    float* __restrict__ out_est)
{
    extern __shared__ float smf[];
    char* sb = (char*)smf;
    __half* w2hi = (__half*)(sb + OFF_W2HI);   // [o][KS]
    __half* w2lo = (__half*)(sb + OFF_W2LO);
    __half* hhi  = (__half*)(sb + OFF_HHI);    // [n][KS]
    float* s_h2 = (float*)(sb + OFF_H2);       // [128][H2ROW]
    float* misc = (float*)(sb + OFF_MISC);
    float* swx  = misc;           // [3][128]
    float* swl  = swx + 384;      // 128
    float* sb2  = swl + 128;      // 128
    float* sw3  = sb2 + 128;      // 384
    float* sb3  = sw3 + 384;      // 4
    float* s_x  = sb3 + 4;        // [3][128]
    float* sred = s_x + 384;      // 8

    const int tid = threadIdx.x;
    const int lane = tid & 31;
    const int wid = tid >> 5;

    // ---- one-time stage: W2 hi/lo (fp16 split), small weights ----
    {
        const int o = tid & 127, kh = tid >> 7;
        const float* w2r = W2 + o * HH;
        for (int k = kh * 64; k < kh * 64 + 64; k += 2) {
            float w0 = w2r[k], w1 = w2r[k + 1];
            __half h0 = __float2half_rn(w0);
            __half h1 = __float2half_rn(w1);
            *(unsigned*)&w2hi[o * KS + k] = pack_hf2(h0, h1);
            *(unsigned*)&w2lo[o * KS + k] =
                pack_hf2(__float2half_rn(w0 - __half2float(h0)),
                         __float2half_rn(w1 - __half2float(h1)));
        }
    }
    for (int i = tid; i < 384; i += 256) {
        int k = i >> 7, o = i & 127;
        swx[k * 128 + o] = W1[o * W1K + k];
        sw3[i] = W3[i];
    }
    if (tid < 128) sb2[tid] = b2[tid];
    if (tid < 3) sb3[tid] = b3[tid];
    __syncthreads();

    const uint32_t u_w2hi = smem_u32(w2hi);
    const uint32_t u_w2lo = smem_u32(w2lo);
    const uint32_t u_hhi  = smem_u32(hhi);

    const int lr = lane & 7;
    const int aq = lane >> 3;
    const int arow_off = ((aq & 1) << 3) + lr;
    const int acol_off = (aq >> 1) << 3;
    const int bl15 = lane & 15;
    const int brow_off = bl15 & 7;
    const int bcol_off = (bl15 >> 3) << 3;

    const int o0 = wid * 16;
    float l2acc = 0.0f;

    for (int t = blockIdx.x; t < NT; t += MLP_GRID) {
        const int b  = t >> 3;
        const int n0 = (t & 7) * TN;

        __syncthreads();
        for (int i = tid; i < 384; i += 256) {
            int k = i >> 7, n = i & 127;
            s_x[k * 128 + n] = pc[(b * 3 + k) * NP + n0 + n];
        }
        if (tid < 128) swl[tid] = g_w1l[b * HH + tid];
        __syncthreads();

        // ---- layer 1 (fp32) -> fp16 h tile [n][k] ----
        {
            const int n = tid & 127, kh = tid >> 7;
            const float x0 = s_x[n], x1 = s_x[128 + n], x2 = s_x[256 + n];
            #pragma unroll
            for (int k = kh * 64; k < kh * 64 + 64; k += 2) {
                float h0 = fmaxf(fmaf(swx[k], x0, fmaf(swx[128 + k], x1,
                             fmaf(swx[256 + k], x2, swl[k]))), 0.0f);
                float h1v = fmaxf(fmaf(swx[k + 1], x0, fmaf(swx[129 + k], x1,
                              fmaf(swx[257 + k], x2, swl[k + 1]))), 0.0f);
                *(unsigned*)&hhi[n * KS + k] =
                    pack_hf2(__float2half_rn(h0), __float2half_rn(h1v));
            }
        }
        __syncthreads();

        // ---- GEMM2: warp o-strip [o0,o0+16), fp16 2-product mma ----
        float C[16][4];
        #pragma unroll
        for (int nt = 0; nt < 16; nt++)
            #pragma unroll
            for (int j = 0; j < 4; j++) C[nt][j] = 0.0f;

        #pragma unroll
        for (int k8 = 0; k8 < 8; k8++) {
            const int k0 = k8 * 16;
            const uint32_t aoff = (uint32_t)(o0 + arow_off) * 272u +
                                  (uint32_t)(k0 + acol_off) * 2u;
            uint32_t ah[4], al[4];
            ldmx4(ah, u_w2hi + aoff);
            ldmx4(al, u_w2lo + aoff);
            #pragma unroll
            for (int nt = 0; nt < 16; nt++) {
                const uint32_t boff = (uint32_t)(nt * 8 + brow_off) * 272u +
                                      (uint32_t)(k0 + bcol_off) * 2u;
                uint32_t bh[2];
                ldmx2(bh, u_hhi + boff);
                mma_f16(C[nt], ah, bh);
                mma_f16(C[nt], al, bh);
            }
        }
        __syncthreads();

        // ---- bias + relu -> s_h2[o][n] ----
        {
            const int r = lane >> 2;
            const int cp = (lane & 3) * 2;
            const float bo  = sb2[o0 + r];
            const float bo8 = sb2[o0 + r + 8];
            #pragma unroll
            for (int nt = 0; nt < 16; nt++) {
                int n = nt * 8 + cp;
                s_h2[(o0 + r) * H2ROW + n]     = fmaxf(C[nt][0] + bo, 0.0f);
                s_h2[(o0 + r) * H2ROW + n + 1] = fmaxf(C[nt][1] + bo, 0.0f);
                s_h2[(o0 + r + 8) * H2ROW + n]     = fmaxf(C[nt][2] + bo8, 0.0f);
                s_h2[(o0 + r + 8) * H2ROW + n + 1] = fmaxf(C[nt][3] + bo8, 0.0f);
            }
        }
        __syncthreads();

        // ---- layer 3 (fp32, 3x128) + epilogue ----
        if (tid < TN) {
            int n = tid, g = n0 + n;
            float o0v = sb3[0], o1v = sb3[1], o2v = sb3[2];
            #pragma unroll 4
            for (int k = 0; k < HH; k++) {
                float hv = s_h2[k * H2ROW + n];
                o0v = fmaf(sw3[k], hv, o0v);
                o1v = fmaf(sw3[128 + k], hv, o1v);
                o2v = fmaf(sw3[256 + k], hv, o2v);
            }
            int base = (b * 3) * NP + g;
            float e0 = pc[base] - o0v;
            float e1 = pc[base + NP] - o1v;
            float e2 = pc[base + 2 * NP] - o2v;
            out_est[base] = e0;
            out_est[base + NP] = e1;
            out_est[base + 2 * NP] = e2;
            float d0 = pc_gt[base] - e0;
            float d1 = pc_gt[base + NP] - e1;
            float d2 = pc_gt[base + 2 * NP] - e2;
            l2acc += fmaf(d0, d0, fmaf(d1, d1, d2 * d2));
        }
    }

    __syncthreads();
    float s = block_sum(l2acc, sred);
    if (tid == 0) atomicAdd(&g_acc[2], s);
}

// ---------------------------------------------------------------------------
// Chamfer (R8 scalar, proven): 512 thr, 4 queries/thread, split m-scan.
// Last CTA to finish also writes the final loss (folds final_kernel).
// ---------------------------------------------------------------------------
__global__ void __launch_bounds__(512) chamfer_kernel(
    const float* __restrict__ pc_gt, const float* __restrict__ est,
    float* __restrict__ out)
{
    __shared__ float4 spts[NP];
    __shared__ float sup[256][4];
    __shared__ float sred[16];
    const int b = blockIdx.x;
    const int dir = blockIdx.y;
    const float* rows  = dir ? est   : pc_gt;
    const float* other = dir ? pc_gt : est;
    const int base = b * 3 * NP;
    const int tid  = threadIdx.x;
    const int qt   = tid & 255;
    const int half = tid >> 8;

    for (int i = tid; i < NP; i += 512) {
        float x = other[base + i];
        float y = other[base + NP + i];
        float z = other[base + 2 * NP + i];
        spts[i] = make_float4(x, y, z, fmaf(x, x, fmaf(y, y, z * z)));
    }
    __syncthreads();

    float qx[4], qy[4], qz[4], qa2[4];
    #pragma unroll
    for (int q = 0; q < 4; q++) {
        int n = qt + q * 256;
        float ax = rows[base + n];
        float ay = rows[base + NP + n];
        float az = rows[base + 2 * NP + n];
        qa2[q] = fmaf(ax, ax, fmaf(ay, ay, az * az));
        qx[q] = -2.0f * ax;
        qy[q] = -2.0f * ay;
        qz[q] = -2.0f * az;
    }

    float bst[4][2];
    #pragma unroll
    for (int q = 0; q < 4; q++) { bst[q][0] = 3.4e38f; bst[q][1] = 3.4e38f; }

    const int m0 = half * 512;
    for (int m = m0; m < m0 + 512; m += 4) {
        float4 p0 = spts[m];
        float4 p1 = spts[m + 1];
        float4 p2 = spts[m + 2];
        float4 p3 = spts[m + 3];
        #pragma unroll
        for (int q = 0; q < 4; q++) {
            float t0 = fmaf(qz[q], p0.z, fmaf(qy[q], p0.y, fmaf(qx[q], p0.x, p0.w)));
            float t1 = fmaf(qz[q], p1.z, fmaf(qy[q], p1.y, fmaf(qx[q], p1.x, p1.w)));
            float t2 = fmaf(qz[q], p2.z, fmaf(qy[q], p2.y, fmaf(qx[q], p2.x, p2.w)));
            float t3 = fmaf(qz[q], p3.z, fmaf(qy[q], p3.y, fmaf(qx[q], p3.x, p3.w)));
            bst[q][0] = fminf(bst[q][0], fminf(t0, t1));
            bst[q][1] = fminf(bst[q][1], fminf(t2, t3));
        }
    }

    if (half) {
        #pragma unroll
        for (int q = 0; q < 4; q++)
            sup[qt][q] = fminf(bst[q][0], bst[q][1]);
    }
    __syncthreads();

    float acc = 0.0f;
    if (!half) {
        #pragma unroll
        for (int q = 0; q < 4; q++) {
            float lo = fminf(bst[q][0], bst[q][1]);
            acc += qa2[q] + fminf(lo, sup[qt][q]);
        }
    }
    float s = block_sum(acc, sred);
    if (tid == 0) {
        atomicAdd(&g_acc[dir], s);
        __threadfence();
        unsigned d = atomicAdd(&g_done, 1u);
        if (d == 2u * BB - 1u) {
            float ch = (g_acc[0] + g_acc[1]) * (1.0f / (float)(BB * NP));
            float l2 = g_acc[2] * (1.0f / (float)(BB * 3 * NP));
            out[0] = 0.1f * ch + 0.9f * l2;
            out[1] = ch;
            out[2] = l2;
        }
    }
}

extern "C" void kernel_launch(void* const* d_in, const int* in_sizes, int n_in,
                              void* d_out, int out_size) {
    const float* pc    = (const float*)d_in[0];
    const float* pc_gt = (const float*)d_in[1];
    const float* lat   = (const float*)d_in[2];
    const float* W1    = (const float*)d_in[3];
    const float* b1    = (const float*)d_in[4];
    const float* W2    = (const float*)d_in[5];
    const float* b2    = (const float*)d_in[6];
    const float* W3    = (const float*)d_in[7];
    const float* b3    = (const float*)d_in[8];
    float* out = (float*)d_out;

    size_t smem_mlp = OFF_MISC + (size_t)(384 + 128 + 128 + 384 + 4 + 384 + 16)
                                 * sizeof(float);
    (void)cudaFuncSetAttribute(mlp_kernel,
                               cudaFuncAttributeMaxDynamicSharedMemorySize,
                               (int)smem_mlp);

    w1l_kernel<<<BB, 128>>>(lat, W1, b1);
    mlp_kernel<<<MLP_GRID, 256, smem_mlp>>>(pc, pc_gt, W2, b2, W1, W3, b3,
                                            out + 3);
    chamfer_kernel<<<dim3(BB, 2), 512>>>(pc_gt, out + 3, out);
}